// round 6
// baseline (speedup 1.0000x reference)
#include <cuda_runtime.h>

// DotProductAttention: B=4, H=8, S=2048, D=16, fp32.
// logits = 10*tanh(QK^T*SCALE); mask(b,key)==1 -> -1e10; softmax; O = P@V.
//
// R6 design:
//  - FFMA2 (fma.rn.f32x2): pack the thread's two queries into f32x2 lanes.
//    K/V smem tiles stored PRE-DUPLICATED (k,k) as u64 so packed operands load
//    directly (no per-key broadcast MOVs). 2x fp32 FMA throughput, exact .rn.
//  - Compacted unmasked-key list per batch (parallel 512-thread scan pre-pass).
//  - Fixed softmax max = 10 => p = exp2(C2/(exp2(C1*q.k)+1)); associative
//    => split-K x8 + deterministic reduce.

#define S_LEN   2048
#define D_DIM   16
#define H_NUM   8
#define B_NUM   4
#define NQ      65536          // B*H*S
#define QT      128            // threads per block
#define QPB     256            // queries per block (2/thread)
#define KT      128            // key tile
#define SPLIT   8
#define KROW    18             // padded u64 row stride (144B: 16B-aligned, 4-way STS)

// C1 = 2*SCALE*log2(e),  C2 = -2*CLIP*log2(e)
#define C1_F  1.1047800f
#define C2_F  (-28.85390082f)

typedef unsigned long long u64;

__device__ float g_pacc[(size_t)SPLIT * NQ * D_DIM];  // 33.5 MB
__device__ float g_psum[(size_t)SPLIT * NQ];          //  2.0 MB
__device__ int   g_kidx[B_NUM][S_LEN];
__device__ int   g_kcnt[B_NUM];

__device__ __forceinline__ float ex2f(float x) {
    float r; asm("ex2.approx.ftz.f32 %0, %1;" : "=f"(r) : "f"(x)); return r;
}
__device__ __forceinline__ float rcpf(float x) {
    float r; asm("rcp.approx.ftz.f32 %0, %1;" : "=f"(r) : "f"(x)); return r;
}
__device__ __forceinline__ u64 pack2(float lo, float hi) {
    u64 r; asm("mov.b64 %0, {%1, %2};" : "=l"(r) : "f"(lo), "f"(hi)); return r;
}
__device__ __forceinline__ void unpack2(u64 v, float& lo, float& hi) {
    asm("mov.b64 {%0, %1}, %2;" : "=f"(lo), "=f"(hi) : "l"(v));
}
__device__ __forceinline__ u64 fma2(u64 a, u64 b, u64 c) {
    u64 d; asm("fma.rn.f32x2 %0, %1, %2, %3;" : "=l"(d) : "l"(a), "l"(b), "l"(c)); return d;
}
__device__ __forceinline__ u64 mul2(u64 a, u64 b) {
    u64 d; asm("mul.rn.f32x2 %0, %1, %2;" : "=l"(d) : "l"(a), "l"(b)); return d;
}
__device__ __forceinline__ u64 add2(u64 a, u64 b) {
    u64 d; asm("add.rn.f32x2 %0, %1, %2;" : "=l"(d) : "l"(a), "l"(b)); return d;
}

// ---- Pre-pass: per-batch compacted unmasked-key list. 1 block/batch, 16 warps. ----
__global__ __launch_bounds__(512)
void compact_kernel(const int* __restrict__ mask)
{
    __shared__ int wcnt[16];
    const int b    = blockIdx.x;
    const int w    = threadIdx.x >> 5;     // 0..15, each owns 128 keys
    const int lane = threadIdx.x & 31;
    const int* Mb  = mask + (size_t)b * S_LEN;
    const int keybase = w * 128;

    unsigned bals[4];
    int cnt = 0;
#pragma unroll
    for (int r = 0; r < 4; r++) {
        int key = keybase + r * 32 + lane;
        bool keep = (Mb[key] == 0);
        unsigned bal = __ballot_sync(0xffffffffu, keep);
        bals[r] = bal;
        cnt += __popc(bal);
    }
    if (lane == 0) wcnt[w] = cnt;
    __syncthreads();

    int base = 0;
    for (int i = 0; i < w; i++) base += wcnt[i];
#pragma unroll
    for (int r = 0; r < 4; r++) {
        int key = keybase + r * 32 + lane;
        unsigned bal = bals[r];
        if ((bal >> lane) & 1u)
            g_kidx[b][base + __popc(bal & ((1u << lane) - 1u))] = key;
        base += __popc(bal);
    }
    if (w == 15 && lane == 0) g_kcnt[b] = base;   // total
}

// ---- Dense inner body: j = compacted slot; all operands f32x2-packed. ----
#define ATTN_BODY(j)                                                               \
{                                                                                  \
    u64 kd[16];                                                                    \
    {                                                                              \
        const ulonglong2* kp2 = reinterpret_cast<const ulonglong2*>(Ksd + (size_t)(j) * KROW); \
        _Pragma("unroll")                                                          \
        for (int i = 0; i < 8; i++) { ulonglong2 t = kp2[i]; kd[2*i] = t.x; kd[2*i+1] = t.y; } \
    }                                                                              \
    u64 t0 = mul2(qp[0], kd[0]);                                                   \
    u64 t1 = mul2(qp[1], kd[1]);                                                   \
    u64 t2 = mul2(qp[2], kd[2]);                                                   \
    u64 t3 = mul2(qp[3], kd[3]);                                                   \
    _Pragma("unroll")                                                              \
    for (int d = 4; d < 16; d += 4) {                                              \
        t0 = fma2(qp[d+0], kd[d+0], t0);                                           \
        t1 = fma2(qp[d+1], kd[d+1], t1);                                           \
        t2 = fma2(qp[d+2], kd[d+2], t2);                                           \
        t3 = fma2(qp[d+3], kd[d+3], t3);                                           \
    }                                                                              \
    u64 dd = add2(add2(t0, t1), add2(t2, t3));                                     \
    float dA, dB; unpack2(dd, dA, dB);                                             \
    float uA = ex2f(dA), uB = ex2f(dB);                                            \
    float pA = ex2f(C2_F * rcpf(uA + 1.0f));                                       \
    float pB = ex2f(C2_F * rcpf(uB + 1.0f));                                       \
    sumA += pA; sumB += pB;                                                        \
    u64 pp = pack2(pA, pB);                                                        \
    {                                                                              \
        const ulonglong2* vp2 = reinterpret_cast<const ulonglong2*>(Vsd + (size_t)(j) * KROW); \
        _Pragma("unroll")                                                          \
        for (int i = 0; i < 8; i++) {                                              \
            ulonglong2 t = vp2[i];                                                 \
            accp[2*i]   = fma2(pp, t.x, accp[2*i]);                                \
            accp[2*i+1] = fma2(pp, t.y, accp[2*i+1]);                              \
        }                                                                          \
    }                                                                              \
}

__global__ __launch_bounds__(QT)
void attn_partial_kernel(const float* __restrict__ Q,
                         const float* __restrict__ K,
                         const float* __restrict__ V)
{
    __shared__ u64 Ksd[KT * KROW];   // duplicated (k,k) pairs, 18 KB
    __shared__ u64 Vsd[KT * KROW];   // duplicated (v,v) pairs, 18 KB

    const int bh    = blockIdx.y;      // 0..31
    const int b     = bh >> 3;         // H = 8
    const int split = blockIdx.z;      // 0..7
    const int tid   = threadIdx.x;
    const int qA    = blockIdx.x * QPB + tid;
    const int qB    = qA + QT;

    const float* Kb = K + (size_t)bh * S_LEN * D_DIM;
    const float* Vb = V + (size_t)bh * S_LEN * D_DIM;

    const int cnt     = g_kcnt[b];
    const int n_tiles = (cnt + KT - 1) / KT;
    const int tps     = (n_tiles + SPLIT - 1) / SPLIT;
    const int t_beg   = split * tps;
    const int t_end   = min(t_beg + tps, n_tiles);

    // Packed queries: qp[d] = (qA_d, qB_d) * C1.
    u64 qp[D_DIM];
    {
        const float4* pa = reinterpret_cast<const float4*>(Q + ((size_t)bh * S_LEN + qA) * D_DIM);
        const float4* pb = reinterpret_cast<const float4*>(Q + ((size_t)bh * S_LEN + qB) * D_DIM);
#pragma unroll
        for (int i = 0; i < 4; i++) {
            float4 ta = pa[i], tb = pb[i];
            qp[4*i+0] = pack2(ta.x * C1_F, tb.x * C1_F);
            qp[4*i+1] = pack2(ta.y * C1_F, tb.y * C1_F);
            qp[4*i+2] = pack2(ta.z * C1_F, tb.z * C1_F);
            qp[4*i+3] = pack2(ta.w * C1_F, tb.w * C1_F);
        }
    }

    u64 accp[D_DIM];
    const u64 zz = pack2(0.0f, 0.0f);
#pragma unroll
    for (int d = 0; d < D_DIM; d++) accp[d] = zz;
    float sumA = 0.0f, sumB = 0.0f;

    for (int t = t_beg; t < t_end; t++) {
        const int base = t * KT;
        const int nv   = min(KT, cnt - base);
        __syncthreads();
        if (tid < nv) {
            const int j = g_kidx[b][base + tid];
            const float4* kp = reinterpret_cast<const float4*>(Kb + (size_t)j * D_DIM);
            const float4* vp = reinterpret_cast<const float4*>(Vb + (size_t)j * D_DIM);
            ulonglong2* kdst = reinterpret_cast<ulonglong2*>(Ksd + (size_t)tid * KROW);
            ulonglong2* vdst = reinterpret_cast<ulonglong2*>(Vsd + (size_t)tid * KROW);
#pragma unroll
            for (int i = 0; i < 4; i++) {
                float4 tk = kp[i], tv = vp[i];
                kdst[2*i+0] = make_ulonglong2(pack2(tk.x, tk.x), pack2(tk.y, tk.y));
                kdst[2*i+1] = make_ulonglong2(pack2(tk.z, tk.z), pack2(tk.w, tk.w));
                vdst[2*i+0] = make_ulonglong2(pack2(tv.x, tv.x), pack2(tv.y, tv.y));
                vdst[2*i+1] = make_ulonglong2(pack2(tv.z, tv.z), pack2(tv.w, tv.w));
            }
        }
        __syncthreads();

        if (nv == KT) {
#pragma unroll 4
            for (int j = 0; j < KT; j++) ATTN_BODY(j);
        } else {
            for (int j = 0; j < nv; j++) ATTN_BODY(j);
        }
    }

    // Write partials (unnormalized).
    const int qiA = bh * S_LEN + qA;
    const int qiB = bh * S_LEN + qB;
    g_psum[(size_t)split * NQ + qiA] = sumA;
    g_psum[(size_t)split * NQ + qiB] = sumB;
    float4* paccA = reinterpret_cast<float4*>(g_pacc + ((size_t)split * NQ + qiA) * D_DIM);
    float4* paccB = reinterpret_cast<float4*>(g_pacc + ((size_t)split * NQ + qiB) * D_DIM);
#pragma unroll
    for (int i = 0; i < 4; i++) {
        float a0, b0, a1, b1, a2, b2, a3, b3;
        unpack2(accp[4*i+0], a0, b0);
        unpack2(accp[4*i+1], a1, b1);
        unpack2(accp[4*i+2], a2, b2);
        unpack2(accp[4*i+3], a3, b3);
        paccA[i] = make_float4(a0, a1, a2, a3);
        paccB[i] = make_float4(b0, b1, b2, b3);
    }
}

__global__ __launch_bounds__(256)
void attn_reduce_kernel(float* __restrict__ O)
{
    const int q = blockIdx.x * 256 + threadIdx.x;   // 0..NQ-1
    float sum = 0.0f;
    float4 a0 = make_float4(0,0,0,0), a1 = a0, a2 = a0, a3 = a0;
#pragma unroll
    for (int s = 0; s < SPLIT; s++) {
        sum += g_psum[(size_t)s * NQ + q];
        const float4* p = reinterpret_cast<const float4*>(g_pacc + ((size_t)s * NQ + q) * D_DIM);
        float4 t0 = p[0], t1 = p[1], t2 = p[2], t3 = p[3];
        a0.x += t0.x; a0.y += t0.y; a0.z += t0.z; a0.w += t0.w;
        a1.x += t1.x; a1.y += t1.y; a1.z += t1.z; a1.w += t1.w;
        a2.x += t2.x; a2.y += t2.y; a2.z += t2.z; a2.w += t2.w;
        a3.x += t3.x; a3.y += t3.y; a3.z += t3.z; a3.w += t3.w;
    }
    float inv = 1.0f / sum;
    float4* op = reinterpret_cast<float4*>(O + (size_t)q * D_DIM);
    op[0] = make_float4(a0.x*inv, a0.y*inv, a0.z*inv, a0.w*inv);
    op[1] = make_float4(a1.x*inv, a1.y*inv, a1.z*inv, a1.w*inv);
    op[2] = make_float4(a2.x*inv, a2.y*inv, a2.z*inv, a2.w*inv);
    op[3] = make_float4(a3.x*inv, a3.y*inv, a3.z*inv, a3.w*inv);
}

extern "C" void kernel_launch(void* const* d_in, const int* in_sizes, int n_in,
                              void* d_out, int out_size)
{
    const float* Q = (const float*)d_in[0];
    const float* K = (const float*)d_in[1];
    const float* V = (const float*)d_in[2];
    const int* mask = (const int*)d_in[3];
    float* O = (float*)d_out;

    compact_kernel<<<B_NUM, 512>>>(mask);
    dim3 grid(S_LEN / QPB, B_NUM * H_NUM, SPLIT);   // (8, 32, 8)
    attn_partial_kernel<<<grid, QT>>>(Q, K, V);
    attn_reduce_kernel<<<NQ / 256, 256>>>(O);
}